// round 2
// baseline (speedup 1.0000x reference)
#include <cuda_runtime.h>
#include <math.h>

// Problem constants (fixed by the reference)
#define EMBED_D 128
#define NCODES  10000
#define NSAMP   16384           // 8*64*32
#define SPLIT   4
#define CODES_PER_SPLIT ((NCODES + SPLIT - 1) / SPLIT)   // 2500

#define MT 128                  // sample tile
#define NT 128                  // code tile per iteration
#define TM 8
#define TN 8
#define THREADS 256

#define AS_LD (MT + 4)          // 132, padded; 132*4B is 16B-aligned

// Device scratch (no allocations allowed)
__device__ float  g_cnorm[NCODES];
__device__ float  g_pscore[NSAMP * SPLIT];
__device__ int    g_pidx[NSAMP * SPLIT];
__device__ double g_ploss[NSAMP / 8];     // one partial per combine block (2048)

// ---------------------------------------------------------------------------
// Kernel 0: per-code squared norms.  cm is (D, C) row-major: cm[k*C + c].
// Consecutive threads -> consecutive c -> coalesced.
// ---------------------------------------------------------------------------
__global__ void cnorm_kernel(const float* __restrict__ cm) {
    int c = blockIdx.x * blockDim.x + threadIdx.x;
    if (c >= NCODES) return;
    float s = 0.f;
#pragma unroll 8
    for (int k = 0; k < EMBED_D; ++k) {
        float v = cm[(size_t)k * NCODES + c];
        s = fmaf(v, v, s);
    }
    g_cnorm[c] = s;
}

// ---------------------------------------------------------------------------
// Kernel 1: fused GEMM + running argmax.
// Block tile: 128 samples x 128 codes, K=128 fully resident.
// grid = (NSAMP/MT, SPLIT); each block scans its code range in NT chunks.
// score(s,c) = x_s . cm_c - 0.5*||cm_c||^2 ; argmin dist == argmax score.
// ---------------------------------------------------------------------------
extern __shared__ float smem_dyn[];

__global__ __launch_bounds__(THREADS, 1)
void vq_argmax_kernel(const float* __restrict__ x, const float* __restrict__ cm) {
    float* As = smem_dyn;                   // [EMBED_D][AS_LD]  (transposed A)
    float* Bs = smem_dyn + EMBED_D * AS_LD; // [EMBED_D][NT]
    float* cn = Bs + EMBED_D * NT;          // [NT]

    const int tid = threadIdx.x;
    const int tx = tid & 15;                // code dim (16)
    const int ty = tid >> 4;                // sample dim (16)
    const int m_base  = blockIdx.x * MT;
    const int c_begin = blockIdx.y * CODES_PER_SPLIT;
    const int c_end   = min(NCODES, c_begin + CODES_PER_SPLIT);

    // ---- Load A tile transposed: As[k][m] = x[(m_base+m)*D + k] ----
    // 4096 float4 positions; p -> m = p>>5 (row), k4 = p&31 (float4 along k).
    // Global reads fully coalesced; smem stores 2-way conflict (pad 132).
#pragma unroll
    for (int it = 0; it < 16; ++it) {
        int p  = tid + it * THREADS;
        int m  = p >> 5;
        int k4 = p & 31;
        float4 v = *(const float4*)(x + (size_t)(m_base + m) * EMBED_D + k4 * 4);
        As[(k4 * 4 + 0) * AS_LD + m] = v.x;
        As[(k4 * 4 + 1) * AS_LD + m] = v.y;
        As[(k4 * 4 + 2) * AS_LD + m] = v.z;
        As[(k4 * 4 + 3) * AS_LD + m] = v.w;
    }

    float bsc[TM];
    int   bix[TM];
#pragma unroll
    for (int i = 0; i < TM; ++i) { bsc[i] = -INFINITY; bix[i] = 0; }

    for (int c0 = c_begin; c0 < c_end; c0 += NT) {
        __syncthreads();   // previous chunk's Bs reads done

        // ---- Load B chunk: Bs[k][n] = cm[k*C + c0+n] (coalesced copy) ----
#pragma unroll
        for (int it = 0; it < 16; ++it) {
            int p  = tid + it * THREADS;
            int k  = p >> 5;
            int n4 = p & 31;
            int c  = c0 + n4 * 4;
            float4 v;
            if (c + 3 < c_end) {
                v = *(const float4*)(cm + (size_t)k * NCODES + c);
            } else {
                v.x = (c + 0 < c_end) ? cm[(size_t)k * NCODES + c + 0] : 0.f;
                v.y = (c + 1 < c_end) ? cm[(size_t)k * NCODES + c + 1] : 0.f;
                v.z = (c + 2 < c_end) ? cm[(size_t)k * NCODES + c + 2] : 0.f;
                v.w = (c + 3 < c_end) ? cm[(size_t)k * NCODES + c + 3] : 0.f;
            }
            *(float4*)(Bs + k * NT + n4 * 4) = v;
        }
        if (tid < NT) {
            int c = c0 + tid;
            cn[tid] = (c < c_end) ? g_cnorm[c] : 0.f;
        }
        __syncthreads();

        // ---- 8x8 register microtile over K=128 ----
        float acc[TM][TN];
#pragma unroll
        for (int i = 0; i < TM; ++i)
#pragma unroll
            for (int j = 0; j < TN; ++j) acc[i][j] = 0.f;

#pragma unroll 4
        for (int k = 0; k < EMBED_D; ++k) {
            float4 a0 = *(const float4*)(As + k * AS_LD + ty * 8);
            float4 a1 = *(const float4*)(As + k * AS_LD + ty * 8 + 4);
            float4 b0 = *(const float4*)(Bs + (k << 7) + tx * 8);
            float4 b1 = *(const float4*)(Bs + (k << 7) + tx * 8 + 4);
            float a[TM] = {a0.x, a0.y, a0.z, a0.w, a1.x, a1.y, a1.z, a1.w};
            float b[TN] = {b0.x, b0.y, b0.z, b0.w, b1.x, b1.y, b1.z, b1.w};
#pragma unroll
            for (int i = 0; i < TM; ++i)
#pragma unroll
                for (int j = 0; j < TN; ++j)
                    acc[i][j] = fmaf(a[i], b[j], acc[i][j]);
        }

        // ---- Fused argmax epilogue (ties -> lowest index, like argmin) ----
#pragma unroll
        for (int j = 0; j < TN; ++j) {
            int c = c0 + tx * 8 + j;
            if (c < c_end) {
                float half_n = 0.5f * cn[tx * 8 + j];
#pragma unroll
                for (int i = 0; i < TM; ++i) {
                    float s = acc[i][j] - half_n;
                    if (s > bsc[i] || (s == bsc[i] && c < bix[i])) {
                        bsc[i] = s; bix[i] = c;
                    }
                }
            }
        }
    }

    // ---- Cross-tx reduction via smem (reuse As region) ----
    __syncthreads();
    float* rs = As;                         // [MT][16] scores
    int*   ri = (int*)(As + MT * 16);       // [MT][16] indices
#pragma unroll
    for (int i = 0; i < TM; ++i) {
        int r = ty * 8 + i;
        rs[r * 16 + tx] = bsc[i];
        ri[r * 16 + tx] = bix[i];
    }
    __syncthreads();
    if (tid < MT) {
        float best = -INFINITY; int bi = 0;
        for (int t = 0; t < 16; ++t) {
            float s = rs[tid * 16 + t];
            int   c = ri[tid * 16 + t];
            if (s > best || (s == best && c < bi)) { best = s; bi = c; }
        }
        int sample = m_base + tid;
        g_pscore[sample * SPLIT + blockIdx.y] = best;
        g_pidx  [sample * SPLIT + blockIdx.y] = bi;
    }
}

// ---------------------------------------------------------------------------
// Kernel 2: combine splits, gather codebook vector, write straight-through
// output, accumulate per-block loss partial (deterministic).
// One warp per sample; 8 samples per block; grid = NSAMP/8 = 2048.
// ---------------------------------------------------------------------------
__global__ __launch_bounds__(256)
void combine_kernel(const float* __restrict__ x, const float* __restrict__ cm,
                    float* __restrict__ out) {
    __shared__ float warp_loss[8];
    int warp = threadIdx.x >> 5;
    int lane = threadIdx.x & 31;
    int s = blockIdx.x * 8 + warp;

    int bi = 0;
    if (lane == 0) {
        float best = -INFINITY;
        for (int t = 0; t < SPLIT; ++t) {
            float sc = g_pscore[s * SPLIT + t];
            int   c  = g_pidx  [s * SPLIT + t];
            if (sc > best || (sc == best && c < bi)) { best = sc; bi = c; }
        }
    }
    bi = __shfl_sync(0xffffffffu, bi, 0);

    float lsum = 0.f;
#pragma unroll
    for (int r = 0; r < 4; ++r) {
        int d = r * 32 + lane;                 // x reads coalesced
        float xv = x[(size_t)s * EMBED_D + d];
        float q  = cm[(size_t)d * NCODES + bi];
        float dlt = q - xv;
        out[(size_t)s * EMBED_D + d] = xv + dlt;  // matches x + (q - x) in fp32
        lsum = fmaf(dlt, dlt, lsum);
    }
    // deterministic warp reduce (fixed shuffle order)
#pragma unroll
    for (int off = 16; off > 0; off >>= 1)
        lsum += __shfl_down_sync(0xffffffffu, lsum, off);
    if (lane == 0) warp_loss[warp] = lsum;
    __syncthreads();
    if (threadIdx.x == 0) {
        double t = 0.0;
        for (int w = 0; w < 8; ++w) t += (double)warp_loss[w];
        g_ploss[blockIdx.x] = t;
    }
}

// ---------------------------------------------------------------------------
// Kernel 3: final loss (fixed sequential order -> deterministic).
// loss = q_loss + 0.25*e_loss = 1.25 * mean((q - x)^2)
// ---------------------------------------------------------------------------
__global__ void loss_kernel(float* __restrict__ out, int out_size) {
    if (out_size <= NSAMP * EMBED_D) return;
    double t = 0.0;
    for (int i = 0; i < NSAMP / 8; ++i) t += g_ploss[i];
    out[NSAMP * EMBED_D] = (float)(1.25 * (t / (double)(NSAMP * EMBED_D)));
}

// ---------------------------------------------------------------------------
extern "C" void kernel_launch(void* const* d_in, const int* in_sizes, int n_in,
                              void* d_out, int out_size) {
    const float* x  = (const float*)d_in[0];   // inputs (8,64,32,128)
    const float* cm = (const float*)d_in[1];   // cluster_mean (128,10000)
    float* out = (float*)d_out;

    const int smem_bytes = (EMBED_D * AS_LD + EMBED_D * NT + NT) * (int)sizeof(float);
    // Idempotent, called every time (no static guards); not a stream op, so
    // it is fine under graph capture.
    (void)cudaFuncSetAttribute(vq_argmax_kernel,
                               cudaFuncAttributeMaxDynamicSharedMemorySize, smem_bytes);

    cnorm_kernel<<<(NCODES + 255) / 256, 256>>>(cm);

    dim3 grid(NSAMP / MT, SPLIT);
    vq_argmax_kernel<<<grid, THREADS, smem_bytes>>>(x, cm);

    combine_kernel<<<NSAMP / 8, 256>>>(x, cm, out);
    loss_kernel<<<1, 1>>>(out, out_size);
}

// round 4
// speedup vs baseline: 1.2122x; 1.2122x over previous
#include <cuda_runtime.h>
#include <math.h>

// Problem constants (fixed by the reference)
#define EMBED_D 128
#define NCODES  10000
#define NSAMP   16384           // 8*64*32
#define SPLIT   8
#define CODES_PER_SPLIT 1280    // multiple of NT -> c0 always 16B-aligned;
                                // split 7 covers 8960..10000 (1040 codes)

#define MT 128                  // sample tile
#define NT 128                  // code tile per iteration
#define TM 8
#define TN 8
#define THREADS 256

#define AS_LD (MT + 4)          // 132, padded; 132*4B is 16B-aligned

// Packed fp32x2 FMA (sm_100+): d = a*b + c elementwise on two packed floats.
// ptxas never auto-generates this from C++ — must be inline PTX.
#define FMA2(d, a, b, c) \
    asm("fma.rn.f32x2 %0, %1, %2, %3;" : "=l"(d) : "l"(a), "l"(b), "l"(c))
#define PACKDUP(d, f) \
    asm("mov.b64 %0, {%1, %1};" : "=l"(d) : "f"(f))
#define UNPACK2(lo, hi, v) \
    asm("mov.b64 {%0, %1}, %2;" : "=f"(lo), "=f"(hi) : "l"(v))

// Device scratch (no allocations allowed)
__device__ float  g_cnorm[NCODES];
__device__ float  g_pscore[NSAMP * SPLIT];
__device__ int    g_pidx[NSAMP * SPLIT];
__device__ double g_ploss[NSAMP / 8];     // one partial per combine block (2048)

// ---------------------------------------------------------------------------
// Kernel 0: per-code squared norms.  cm is (D, C) row-major: cm[k*C + c].
// ---------------------------------------------------------------------------
__global__ void cnorm_kernel(const float* __restrict__ cm) {
    int c = blockIdx.x * blockDim.x + threadIdx.x;
    if (c >= NCODES) return;
    float s = 0.f;
#pragma unroll 8
    for (int k = 0; k < EMBED_D; ++k) {
        float v = cm[(size_t)k * NCODES + c];
        s = fmaf(v, v, s);
    }
    g_cnorm[c] = s;
}

// ---------------------------------------------------------------------------
// Kernel 1: fused GEMM + running argmax, FFMA2 inner loop.
// Block tile: 128 samples x 128 codes, K=128 fully resident.
// grid = (NSAMP/MT, SPLIT); each block scans its code range in NT chunks.
// score(s,c) = x_s . cm_c - 0.5*||cm_c||^2 ; argmin dist == argmax score.
// ---------------------------------------------------------------------------
extern __shared__ float smem_dyn[];

__global__ __launch_bounds__(THREADS, 1)
void vq_argmax_kernel(const float* __restrict__ x, const float* __restrict__ cm) {
    float* As = smem_dyn;                   // [EMBED_D][AS_LD]  (transposed A)
    float* Bs = smem_dyn + EMBED_D * AS_LD; // [EMBED_D][NT]
    float* cn = Bs + EMBED_D * NT;          // [NT]

    const int tid = threadIdx.x;
    const int tx = tid & 15;                // code dim (16)
    const int ty = tid >> 4;                // sample dim (16)
    const int m_base  = blockIdx.x * MT;
    const int c_begin = blockIdx.y * CODES_PER_SPLIT;
    const int c_end   = min(NCODES, c_begin + CODES_PER_SPLIT);

    // ---- Load A tile transposed: As[k][m] = x[(m_base+m)*D + k] ----
#pragma unroll
    for (int it = 0; it < 16; ++it) {
        int p  = tid + it * THREADS;
        int m  = p >> 5;
        int k4 = p & 31;
        float4 v = *(const float4*)(x + (size_t)(m_base + m) * EMBED_D + k4 * 4);
        As[(k4 * 4 + 0) * AS_LD + m] = v.x;
        As[(k4 * 4 + 1) * AS_LD + m] = v.y;
        As[(k4 * 4 + 2) * AS_LD + m] = v.z;
        As[(k4 * 4 + 3) * AS_LD + m] = v.w;
    }

    float bsc[TM];
    int   bix[TM];
#pragma unroll
    for (int i = 0; i < TM; ++i) { bsc[i] = -INFINITY; bix[i] = 0; }

    for (int c0 = c_begin; c0 < c_end; c0 += NT) {
        __syncthreads();   // previous chunk's Bs reads done

        // ---- Load B chunk: Bs[k][n] = cm[k*C + c0+n] (coalesced copy) ----
        // c0 is always a multiple of 128 -> float4 base aligned.
#pragma unroll
        for (int it = 0; it < 16; ++it) {
            int p  = tid + it * THREADS;
            int k  = p >> 5;
            int n4 = p & 31;
            int c  = c0 + n4 * 4;
            float4 v;
            if (c + 3 < c_end) {
                v = *(const float4*)(cm + (size_t)k * NCODES + c);
            } else {
                v.x = (c + 0 < c_end) ? cm[(size_t)k * NCODES + c + 0] : 0.f;
                v.y = (c + 1 < c_end) ? cm[(size_t)k * NCODES + c + 1] : 0.f;
                v.z = (c + 2 < c_end) ? cm[(size_t)k * NCODES + c + 2] : 0.f;
                v.w = (c + 3 < c_end) ? cm[(size_t)k * NCODES + c + 3] : 0.f;
            }
            *(float4*)(Bs + k * NT + n4 * 4) = v;
        }
        if (tid < NT) {
            int c = c0 + tid;
            cn[tid] = (c < c_end) ? g_cnorm[c] : 0.f;
        }
        __syncthreads();

        // ---- 8x8 microtile over K=128, packed f32x2 FMAs ----
        // acc2[i][j2] packs codes (2*j2, 2*j2+1): b-pairs load pre-packed
        // from Bs (codes contiguous); a values duplicated into pairs.
        unsigned long long acc2[TM][TN / 2];
#pragma unroll
        for (int i = 0; i < TM; ++i)
#pragma unroll
            for (int j = 0; j < TN / 2; ++j) acc2[i][j] = 0ULL;

#pragma unroll 4
        for (int k = 0; k < EMBED_D; ++k) {
            // b: 8 contiguous codes -> 4 packed operands, zero pack cost
            ulonglong2 bv0 = *(const ulonglong2*)(Bs + (k << 7) + tx * 8);
            ulonglong2 bv1 = *(const ulonglong2*)(Bs + (k << 7) + tx * 8 + 4);
            unsigned long long b2[4] = {bv0.x, bv0.y, bv1.x, bv1.y};
            // a: 8 sample values, each duplicated into a pair
            float4 a0 = *(const float4*)(As + k * AS_LD + ty * 8);
            float4 a1 = *(const float4*)(As + k * AS_LD + ty * 8 + 4);
            float a[TM] = {a0.x, a0.y, a0.z, a0.w, a1.x, a1.y, a1.z, a1.w};
            unsigned long long pa[TM];
#pragma unroll
            for (int i = 0; i < TM; ++i) PACKDUP(pa[i], a[i]);
#pragma unroll
            for (int i = 0; i < TM; ++i)
#pragma unroll
                for (int j = 0; j < TN / 2; ++j)
                    FMA2(acc2[i][j], pa[i], b2[j], acc2[i][j]);
        }

        // ---- Fused argmax epilogue (ties -> lowest index, like argmin) ----
#pragma unroll
        for (int j2 = 0; j2 < TN / 2; ++j2) {
#pragma unroll
            for (int h = 0; h < 2; ++h) {
                int jn = 2 * j2 + h;
                int c  = c0 + tx * 8 + jn;
                if (c < c_end) {
                    float half_n = 0.5f * cn[tx * 8 + jn];
#pragma unroll
                    for (int i = 0; i < TM; ++i) {
                        float lo, hi;
                        UNPACK2(lo, hi, acc2[i][j2]);
                        float v = h ? hi : lo;
                        float s = v - half_n;
                        if (s > bsc[i] || (s == bsc[i] && c < bix[i])) {
                            bsc[i] = s; bix[i] = c;
                        }
                    }
                }
            }
        }
    }

    // ---- Cross-tx reduction via smem (reuse As region) ----
    __syncthreads();
    float* rs = As;                         // [MT][16] scores
    int*   ri = (int*)(As + MT * 16);       // [MT][16] indices
#pragma unroll
    for (int i = 0; i < TM; ++i) {
        int r = ty * 8 + i;
        rs[r * 16 + tx] = bsc[i];
        ri[r * 16 + tx] = bix[i];
    }
    __syncthreads();
    if (tid < MT) {
        float best = -INFINITY; int bi = 0;
        for (int t = 0; t < 16; ++t) {
            float s = rs[tid * 16 + t];
            int   c = ri[tid * 16 + t];
            if (s > best || (s == best && c < bi)) { best = s; bi = c; }
        }
        int sample = m_base + tid;
        g_pscore[sample * SPLIT + blockIdx.y] = best;
        g_pidx  [sample * SPLIT + blockIdx.y] = bi;
    }
}

// ---------------------------------------------------------------------------
// Kernel 2: combine splits, gather codebook vector, write straight-through
// output, accumulate per-block loss partial (deterministic).
// ---------------------------------------------------------------------------
__global__ __launch_bounds__(256)
void combine_kernel(const float* __restrict__ x, const float* __restrict__ cm,
                    float* __restrict__ out) {
    __shared__ float warp_loss[8];
    int warp = threadIdx.x >> 5;
    int lane = threadIdx.x & 31;
    int s = blockIdx.x * 8 + warp;

    int bi = 0;
    if (lane == 0) {
        float best = -INFINITY;
        for (int t = 0; t < SPLIT; ++t) {
            float sc = g_pscore[s * SPLIT + t];
            int   c  = g_pidx  [s * SPLIT + t];
            if (sc > best || (sc == best && c < bi)) { best = sc; bi = c; }
        }
    }
    bi = __shfl_sync(0xffffffffu, bi, 0);

    float lsum = 0.f;
#pragma unroll
    for (int r = 0; r < 4; ++r) {
        int d = r * 32 + lane;                 // x reads coalesced
        float xv = x[(size_t)s * EMBED_D + d];
        float q  = cm[(size_t)d * NCODES + bi];
        float dlt = q - xv;
        out[(size_t)s * EMBED_D + d] = xv + dlt;  // matches x + (q - x) in fp32
        lsum = fmaf(dlt, dlt, lsum);
    }
#pragma unroll
    for (int off = 16; off > 0; off >>= 1)
        lsum += __shfl_down_sync(0xffffffffu, lsum, off);
    if (lane == 0) warp_loss[warp] = lsum;
    __syncthreads();
    if (threadIdx.x == 0) {
        double t = 0.0;
        for (int w = 0; w < 8; ++w) t += (double)warp_loss[w];
        g_ploss[blockIdx.x] = t;
    }
}

// ---------------------------------------------------------------------------
// Kernel 3: final loss. Parallel, fixed-order -> deterministic.
// loss = q_loss + 0.25*e_loss = 1.25 * mean((q - x)^2)
// ---------------------------------------------------------------------------
__global__ __launch_bounds__(256)
void loss_kernel(float* __restrict__ out, int out_size) {
    if (out_size <= NSAMP * EMBED_D) return;
    __shared__ double sd[256];
    int tid = threadIdx.x;
    double t = 0.0;
    for (int i = tid; i < NSAMP / 8; i += 256) t += g_ploss[i];
    sd[tid] = t;
    __syncthreads();
#pragma unroll
    for (int off = 128; off > 0; off >>= 1) {
        if (tid < off) sd[tid] += sd[tid + off];
        __syncthreads();
    }
    if (tid == 0)
        out[NSAMP * EMBED_D] = (float)(1.25 * (sd[0] / (double)(NSAMP * EMBED_D)));
}

// ---------------------------------------------------------------------------
extern "C" void kernel_launch(void* const* d_in, const int* in_sizes, int n_in,
                              void* d_out, int out_size) {
    const float* x  = (const float*)d_in[0];   // inputs (8,64,32,128)
    const float* cm = (const float*)d_in[1];   // cluster_mean (128,10000)
    float* out = (float*)d_out;

    const int smem_bytes = (EMBED_D * AS_LD + EMBED_D * NT + NT) * (int)sizeof(float);
    (void)cudaFuncSetAttribute(vq_argmax_kernel,
                               cudaFuncAttributeMaxDynamicSharedMemorySize, smem_bytes);

    cnorm_kernel<<<(NCODES + 255) / 256, 256>>>(cm);

    dim3 grid(NSAMP / MT, SPLIT);
    vq_argmax_kernel<<<grid, THREADS, smem_bytes>>>(x, cm);

    combine_kernel<<<NSAMP / 8, 256>>>(x, cm, out);
    loss_kernel<<<1, 256>>>(out, out_size);
}

// round 5
// speedup vs baseline: 1.2127x; 1.0004x over previous
#include <cuda_runtime.h>
#include <math.h>

// Problem constants (fixed by the reference)
#define EMBED_D 128
#define NCODES  10000
#define NSAMP   16384           // 8*64*32
#define SPLIT   8
#define CODES_PER_SPLIT 1280    // multiple of NT -> c0 always 16B-aligned;
                                // split 7 covers 8960..10000 (1040 codes)

#define MT 128                  // sample tile
#define NT 128                  // code tile per iteration
#define TM 8
#define TN 8
#define THREADS 256

#define AS_LD (MT + 4)          // 132, padded; 132*4B is 16B-aligned

// Packed fp32x2 FMA (sm_100+): d = a*b + c elementwise on two packed floats.
// ptxas never auto-generates this from C++ — must be inline PTX.
#define FMA2(d, a, b, c) \
    asm("fma.rn.f32x2 %0, %1, %2, %3;" : "=l"(d) : "l"(a), "l"(b), "l"(c))
#define PACKDUP(d, f) \
    asm("mov.b64 %0, {%1, %1};" : "=l"(d) : "f"(f))
#define UNPACK2(lo, hi, v) \
    asm("mov.b64 {%0, %1}, %2;" : "=f"(lo), "=f"(hi) : "l"(v))

// Device scratch (no allocations allowed)
__device__ float  g_cnorm[NCODES];
__device__ float  g_pscore[NSAMP * SPLIT];
__device__ int    g_pidx[NSAMP * SPLIT];
__device__ double g_ploss[NSAMP / 8];     // one partial per combine block (2048)

// ---------------------------------------------------------------------------
// Kernel 0: per-code squared norms.  cm is (D, C) row-major: cm[k*C + c].
// ---------------------------------------------------------------------------
__global__ void cnorm_kernel(const float* __restrict__ cm) {
    int c = blockIdx.x * blockDim.x + threadIdx.x;
    if (c >= NCODES) return;
    float s = 0.f;
#pragma unroll 8
    for (int k = 0; k < EMBED_D; ++k) {
        float v = cm[(size_t)k * NCODES + c];
        s = fmaf(v, v, s);
    }
    g_cnorm[c] = s;
}

// ---------------------------------------------------------------------------
// Kernel 1: fused GEMM + running argmax, FFMA2 inner loop.
// Block tile: 128 samples x 128 codes, K=128 fully resident.
// grid = (NSAMP/MT, SPLIT); each block scans its code range in NT chunks.
// score(s,c) = x_s . cm_c - 0.5*||cm_c||^2 ; argmin dist == argmax score.
// ---------------------------------------------------------------------------
extern __shared__ float smem_dyn[];

__global__ __launch_bounds__(THREADS, 1)
void vq_argmax_kernel(const float* __restrict__ x, const float* __restrict__ cm) {
    float* As = smem_dyn;                   // [EMBED_D][AS_LD]  (transposed A)
    float* Bs = smem_dyn + EMBED_D * AS_LD; // [EMBED_D][NT]
    float* cn = Bs + EMBED_D * NT;          // [NT]

    const int tid = threadIdx.x;
    const int tx = tid & 15;                // code dim (16)
    const int ty = tid >> 4;                // sample dim (16)
    const int m_base  = blockIdx.x * MT;
    const int c_begin = blockIdx.y * CODES_PER_SPLIT;
    const int c_end   = min(NCODES, c_begin + CODES_PER_SPLIT);

    // ---- Load A tile transposed: As[k][m] = x[(m_base+m)*D + k] ----
#pragma unroll
    for (int it = 0; it < 16; ++it) {
        int p  = tid + it * THREADS;
        int m  = p >> 5;
        int k4 = p & 31;
        float4 v = *(const float4*)(x + (size_t)(m_base + m) * EMBED_D + k4 * 4);
        As[(k4 * 4 + 0) * AS_LD + m] = v.x;
        As[(k4 * 4 + 1) * AS_LD + m] = v.y;
        As[(k4 * 4 + 2) * AS_LD + m] = v.z;
        As[(k4 * 4 + 3) * AS_LD + m] = v.w;
    }

    float bsc[TM];
    int   bix[TM];
#pragma unroll
    for (int i = 0; i < TM; ++i) { bsc[i] = -INFINITY; bix[i] = 0; }

    for (int c0 = c_begin; c0 < c_end; c0 += NT) {
        __syncthreads();   // previous chunk's Bs reads done

        // ---- Load B chunk: Bs[k][n] = cm[k*C + c0+n] (coalesced copy) ----
        // c0 is always a multiple of 128 -> float4 base aligned.
#pragma unroll
        for (int it = 0; it < 16; ++it) {
            int p  = tid + it * THREADS;
            int k  = p >> 5;
            int n4 = p & 31;
            int c  = c0 + n4 * 4;
            float4 v;
            if (c + 3 < c_end) {
                v = *(const float4*)(cm + (size_t)k * NCODES + c);
            } else {
                v.x = (c + 0 < c_end) ? cm[(size_t)k * NCODES + c + 0] : 0.f;
                v.y = (c + 1 < c_end) ? cm[(size_t)k * NCODES + c + 1] : 0.f;
                v.z = (c + 2 < c_end) ? cm[(size_t)k * NCODES + c + 2] : 0.f;
                v.w = (c + 3 < c_end) ? cm[(size_t)k * NCODES + c + 3] : 0.f;
            }
            *(float4*)(Bs + k * NT + n4 * 4) = v;
        }
        if (tid < NT) {
            int c = c0 + tid;
            cn[tid] = (c < c_end) ? g_cnorm[c] : 0.f;
        }
        __syncthreads();

        // ---- 8x8 microtile over K=128, packed f32x2 FMAs ----
        // acc2[i][j2] packs codes (2*j2, 2*j2+1): b-pairs load pre-packed
        // from Bs (codes contiguous); a values duplicated into pairs.
        unsigned long long acc2[TM][TN / 2];
#pragma unroll
        for (int i = 0; i < TM; ++i)
#pragma unroll
            for (int j = 0; j < TN / 2; ++j) acc2[i][j] = 0ULL;

#pragma unroll 4
        for (int k = 0; k < EMBED_D; ++k) {
            // b: 8 contiguous codes -> 4 packed operands, zero pack cost
            ulonglong2 bv0 = *(const ulonglong2*)(Bs + (k << 7) + tx * 8);
            ulonglong2 bv1 = *(const ulonglong2*)(Bs + (k << 7) + tx * 8 + 4);
            unsigned long long b2[4] = {bv0.x, bv0.y, bv1.x, bv1.y};
            // a: 8 sample values, each duplicated into a pair
            float4 a0 = *(const float4*)(As + k * AS_LD + ty * 8);
            float4 a1 = *(const float4*)(As + k * AS_LD + ty * 8 + 4);
            float a[TM] = {a0.x, a0.y, a0.z, a0.w, a1.x, a1.y, a1.z, a1.w};
            unsigned long long pa[TM];
#pragma unroll
            for (int i = 0; i < TM; ++i) PACKDUP(pa[i], a[i]);
#pragma unroll
            for (int i = 0; i < TM; ++i)
#pragma unroll
                for (int j = 0; j < TN / 2; ++j)
                    FMA2(acc2[i][j], pa[i], b2[j], acc2[i][j]);
        }

        // ---- Fused argmax epilogue (ties -> lowest index, like argmin) ----
#pragma unroll
        for (int j2 = 0; j2 < TN / 2; ++j2) {
#pragma unroll
            for (int h = 0; h < 2; ++h) {
                int jn = 2 * j2 + h;
                int c  = c0 + tx * 8 + jn;
                if (c < c_end) {
                    float half_n = 0.5f * cn[tx * 8 + jn];
#pragma unroll
                    for (int i = 0; i < TM; ++i) {
                        float lo, hi;
                        UNPACK2(lo, hi, acc2[i][j2]);
                        float v = h ? hi : lo;
                        float s = v - half_n;
                        if (s > bsc[i] || (s == bsc[i] && c < bix[i])) {
                            bsc[i] = s; bix[i] = c;
                        }
                    }
                }
            }
        }
    }

    // ---- Cross-tx reduction via smem (reuse As region) ----
    __syncthreads();
    float* rs = As;                         // [MT][16] scores
    int*   ri = (int*)(As + MT * 16);       // [MT][16] indices
#pragma unroll
    for (int i = 0; i < TM; ++i) {
        int r = ty * 8 + i;
        rs[r * 16 + tx] = bsc[i];
        ri[r * 16 + tx] = bix[i];
    }
    __syncthreads();
    if (tid < MT) {
        float best = -INFINITY; int bi = 0;
        for (int t = 0; t < 16; ++t) {
            float s = rs[tid * 16 + t];
            int   c = ri[tid * 16 + t];
            if (s > best || (s == best && c < bi)) { best = s; bi = c; }
        }
        int sample = m_base + tid;
        g_pscore[sample * SPLIT + blockIdx.y] = best;
        g_pidx  [sample * SPLIT + blockIdx.y] = bi;
    }
}

// ---------------------------------------------------------------------------
// Kernel 2: combine splits, gather codebook vector, write straight-through
// output, accumulate per-block loss partial (deterministic).
// ---------------------------------------------------------------------------
__global__ __launch_bounds__(256)
void combine_kernel(const float* __restrict__ x, const float* __restrict__ cm,
                    float* __restrict__ out) {
    __shared__ float warp_loss[8];
    int warp = threadIdx.x >> 5;
    int lane = threadIdx.x & 31;
    int s = blockIdx.x * 8 + warp;

    int bi = 0;
    if (lane == 0) {
        float best = -INFINITY;
        for (int t = 0; t < SPLIT; ++t) {
            float sc = g_pscore[s * SPLIT + t];
            int   c  = g_pidx  [s * SPLIT + t];
            if (sc > best || (sc == best && c < bi)) { best = sc; bi = c; }
        }
    }
    bi = __shfl_sync(0xffffffffu, bi, 0);

    float lsum = 0.f;
#pragma unroll
    for (int r = 0; r < 4; ++r) {
        int d = r * 32 + lane;                 // x reads coalesced
        float xv = x[(size_t)s * EMBED_D + d];
        float q  = cm[(size_t)d * NCODES + bi];
        float dlt = q - xv;
        out[(size_t)s * EMBED_D + d] = xv + dlt;  // matches x + (q - x) in fp32
        lsum = fmaf(dlt, dlt, lsum);
    }
#pragma unroll
    for (int off = 16; off > 0; off >>= 1)
        lsum += __shfl_down_sync(0xffffffffu, lsum, off);
    if (lane == 0) warp_loss[warp] = lsum;
    __syncthreads();
    if (threadIdx.x == 0) {
        double t = 0.0;
        for (int w = 0; w < 8; ++w) t += (double)warp_loss[w];
        g_ploss[blockIdx.x] = t;
    }
}

// ---------------------------------------------------------------------------
// Kernel 3: final loss. Parallel, fixed-order -> deterministic.
// loss = q_loss + 0.25*e_loss = 1.25 * mean((q - x)^2)
// ---------------------------------------------------------------------------
__global__ __launch_bounds__(256)
void loss_kernel(float* __restrict__ out, int out_size) {
    if (out_size <= NSAMP * EMBED_D) return;
    __shared__ double sd[256];
    int tid = threadIdx.x;
    double t = 0.0;
    for (int i = tid; i < NSAMP / 8; i += 256) t += g_ploss[i];
    sd[tid] = t;
    __syncthreads();
#pragma unroll
    for (int off = 128; off > 0; off >>= 1) {
        if (tid < off) sd[tid] += sd[tid + off];
        __syncthreads();
    }
    if (tid == 0)
        out[NSAMP * EMBED_D] = (float)(1.25 * (sd[0] / (double)(NSAMP * EMBED_D)));
}

// ---------------------------------------------------------------------------
extern "C" void kernel_launch(void* const* d_in, const int* in_sizes, int n_in,
                              void* d_out, int out_size) {
    const float* x  = (const float*)d_in[0];   // inputs (8,64,32,128)
    const float* cm = (const float*)d_in[1];   // cluster_mean (128,10000)
    float* out = (float*)d_out;

    const int smem_bytes = (EMBED_D * AS_LD + EMBED_D * NT + NT) * (int)sizeof(float);
    (void)cudaFuncSetAttribute(vq_argmax_kernel,
                               cudaFuncAttributeMaxDynamicSharedMemorySize, smem_bytes);

    cnorm_kernel<<<(NCODES + 255) / 256, 256>>>(cm);

    dim3 grid(NSAMP / MT, SPLIT);
    vq_argmax_kernel<<<grid, THREADS, smem_bytes>>>(x, cm);

    combine_kernel<<<NSAMP / 8, 256>>>(x, cm, out);
    loss_kernel<<<1, 256>>>(out, out_size);
}

// round 7
// speedup vs baseline: 3.8580x; 3.1815x over previous
#include <cuda_runtime.h>
#include <cuda_bf16.h>
#include <cstdint>
#include <math.h>

// ---------------- problem constants ----------------
#define EMBED_D 128
#define NCODES  10000
#define NPADC   10112          // 79 * 128
#define NSAMP   16384          // 8*64*32
#define NCHUNK  79
#define NBLK    1264           // NPADC / 8 blocks of 8 codes
#define P1_THREADS 256

// smem layout for pass1 (bytes)
#define SM1_A   0              // 128 x 256B (bf16 [m][k], SW256)
#define SM1_B   32768          // 2 stages x 128 x 256B (bf16 [code][k], SW256)
#define SM1_CN  98304          // 2 stages x 128 floats
#define SM1_TOTAL 99328

// ---------------- device scratch ----------------
__device__ __align__(16) __nv_bfloat16 g_xb[NSAMP * EMBED_D];   // [m][k]
__device__ __align__(16) __nv_bfloat16 g_cb[NPADC * EMBED_D];   // [c][k]
__device__ __align__(16) float g_cnorm[NPADC];                  // pad = +inf
__device__ float  g_bmax[(size_t)NSAMP * NBLK];                 // coarse per-8 maxima
__device__ int    g_maxcn_bits = 0;                             // max ||c||^2 (bits)
__device__ int    g_pidx[NSAMP];
__device__ double g_ploss[NSAMP / 8];

// ---------------- PTX helpers (all baseline sm_80-class ISA) ----------------
__device__ __forceinline__ uint32_t smem_u32(const void* p) {
    uint32_t a;
    asm("{ .reg .u64 t; cvta.to.shared.u64 t, %1; cvt.u32.u64 %0, t; }"
        : "=r"(a) : "l"(p));
    return a;
}
#define CP16(dst, src) \
    asm volatile("cp.async.cg.shared.global [%0], [%1], 16;" :: "r"(dst), "l"(src) : "memory")
#define CP_COMMIT() asm volatile("cp.async.commit_group;" ::: "memory")
#define CP_WAIT0()  asm volatile("cp.async.wait_group 0;" ::: "memory")
#define LDM4(r, addr) \
    asm volatile("ldmatrix.sync.aligned.m8n8.x4.shared.b16 {%0,%1,%2,%3}, [%4];" \
        : "=r"((r)[0]), "=r"((r)[1]), "=r"((r)[2]), "=r"((r)[3]) : "r"(addr))
#define MMA16816(d, a, b) \
    asm volatile("mma.sync.aligned.m16n8k16.row.col.f32.bf16.bf16.f32 " \
        "{%0,%1,%2,%3}, {%4,%5,%6,%7}, {%8,%9}, {%0,%1,%2,%3};" \
        : "+f"((d)[0]), "+f"((d)[1]), "+f"((d)[2]), "+f"((d)[3]) \
        : "r"((a)[0]), "r"((a)[1]), "r"((a)[2]), "r"((a)[3]), "r"((b)[0]), "r"((b)[1]))

// ---------------------------------------------------------------------------
// prep: x -> bf16 [m][k]
// ---------------------------------------------------------------------------
__global__ void conv_x_kernel(const float* __restrict__ x) {
    int i = blockIdx.x * blockDim.x + threadIdx.x;
    if (i < NSAMP * EMBED_D) g_xb[i] = __float2bfloat16_rn(x[i]);
}

// ---------------------------------------------------------------------------
// prep: cm [k][c] -> bf16 [c][k], zero-padded codes
// ---------------------------------------------------------------------------
__global__ void conv_cm_kernel(const float* __restrict__ cm) {
    __shared__ float tile[32][33];
    int ct = blockIdx.x, kt = blockIdx.y;
    int tx = threadIdx.x & 31, ty = threadIdx.x >> 5;   // ty 0..7
#pragma unroll
    for (int i = 0; i < 4; ++i) {
        int kr = ty + i * 8;
        int c = ct * 32 + tx;
        tile[kr][tx] = (c < NCODES) ? cm[(size_t)(kt * 32 + kr) * NCODES + c] : 0.f;
    }
    __syncthreads();
#pragma unroll
    for (int i = 0; i < 4; ++i) {
        int cr = ty + i * 8;
        int c = ct * 32 + cr;
        int k = kt * 32 + tx;
        g_cb[(size_t)c * EMBED_D + k] = __float2bfloat16_rn(tile[tx][cr]);
    }
}

// ---------------------------------------------------------------------------
// prep: per-code squared norms (exact fp32), pad=+inf; track max norm
// ---------------------------------------------------------------------------
__global__ void cnorm_kernel(const float* __restrict__ cm) {
    int c = blockIdx.x * blockDim.x + threadIdx.x;
    if (c >= NPADC) return;
    if (c >= NCODES) { g_cnorm[c] = INFINITY; return; }
    float s = 0.f;
#pragma unroll 8
    for (int k = 0; k < EMBED_D; ++k) {
        float v = cm[(size_t)k * NCODES + c];
        s = fmaf(v, v, s);
    }
    g_cnorm[c] = s;
    atomicMax(&g_maxcn_bits, __float_as_int(s));   // positive floats: int order == float order
}

// ---------------------------------------------------------------------------
// pass 1: coarse bf16 GEMM (mma.sync) + per-8-code block maxima of
// score(s,c) = <x_s, c> - 0.5*||c||^2.  128 CTAs x 256 thr; CTA owns
// 128 samples, streams 79 chunks of 128 codes. SW256 swizzled smem.
// ---------------------------------------------------------------------------
extern __shared__ char smem1[];

__device__ __forceinline__ void p1_load_B(uint32_t sb, int chunk, int st, int tid) {
    int c0 = chunk * 128;
#pragma unroll
    for (int i = 0; i < 8; ++i) {
        int p = tid + i * P1_THREADS;
        int row = p >> 4, c16 = p & 15;
        const __nv_bfloat16* src = &g_cb[(size_t)(c0 + row) * EMBED_D + c16 * 8];
        uint32_t dst = sb + SM1_B + st * 32768 + row * 256 + ((c16 * 16) ^ ((row & 7) << 4));
        CP16(dst, src);
    }
    if (tid < 32)
        CP16(sb + SM1_CN + st * 512 + tid * 16, &g_cnorm[c0 + tid * 4]);
}

__global__ __launch_bounds__(P1_THREADS, 1)
void coarse_kernel() {
    const int tid  = threadIdx.x;
    const int lane = tid & 31;
    const int wid  = tid >> 5;
    const int wm   = wid & 3;          // warp m group: rows wm*32..+31
    const int wn   = wid >> 2;         // warp n group: codes wn*64..+63
    const int m_base = blockIdx.x * 128;
    uint32_t sb = smem_u32(smem1);

    // ---- A tile load: g_xb rows m_base..+127 ----
#pragma unroll
    for (int i = 0; i < 8; ++i) {
        int p = tid + i * P1_THREADS;
        int row = p >> 4, c16 = p & 15;
        const __nv_bfloat16* src = &g_xb[(size_t)(m_base + row) * EMBED_D + c16 * 8];
        uint32_t dst = sb + SM1_A + row * 256 + ((c16 * 16) ^ ((row & 7) << 4));
        CP16(dst, src);
    }
    p1_load_B(sb, 0, 0, tid);
    CP_COMMIT();
    CP_WAIT0();
    __syncthreads();

    // ---- per-lane ldmatrix geometry ----
    // A x4: matrices (m0-7,k0),(m8-15,k0),(m0-7,k8),(m8-15,k8)
    int a_row_loc = (lane & 7) | (lane & 8);
    int a_kb      = (lane & 16);                 // +16B if k+8 half
    uint32_t a_base[2], a_xor[2];
#pragma unroll
    for (int mt = 0; mt < 2; ++mt) {
        int row = wm * 32 + mt * 16 + a_row_loc;
        a_base[mt] = sb + SM1_A + row * 256;
        a_xor[mt]  = (row & 7) << 4;
    }
    // B x4: matrices (nt0,k0),(nt0,k8),(nt1,k0),(nt1,k8) for an n16 pair
    int b_row_loc = (lane & 7) | ((lane >> 1) & 8);   // +8 rows for lanes>=16
    int b_kb      = (lane & 8) << 1;                  // +16B for lanes 8-15,24-31
    int b_rowrel[4], b_xor[4];
#pragma unroll
    for (int np = 0; np < 4; ++np) {
        int row = wn * 64 + np * 16 + b_row_loc;
        b_rowrel[np] = row * 256;
        b_xor[np]    = (row & 7) << 4;
    }

    for (int t = 0; t < NCHUNK; ++t) {
        int st = t & 1;
        if (t + 1 < NCHUNK) p1_load_B(sb, t + 1, st ^ 1, tid);
        CP_COMMIT();

        uint32_t bst = sb + SM1_B + st * 32768;
        float acc[2][8][4];
#pragma unroll
        for (int mt = 0; mt < 2; ++mt)
#pragma unroll
            for (int nt = 0; nt < 8; ++nt)
#pragma unroll
                for (int r = 0; r < 4; ++r) acc[mt][nt][r] = 0.f;

#pragma unroll
        for (int ks = 0; ks < 8; ++ks) {
            int kb = ks * 32;
            uint32_t aR[2][4];
#pragma unroll
            for (int mt = 0; mt < 2; ++mt)
                LDM4(aR[mt], a_base[mt] + ((kb + a_kb) ^ a_xor[mt]));
            uint32_t bR[4][4];
#pragma unroll
            for (int np = 0; np < 4; ++np)
                LDM4(bR[np], bst + b_rowrel[np] + ((kb + b_kb) ^ b_xor[np]));
#pragma unroll
            for (int mt = 0; mt < 2; ++mt)
#pragma unroll
                for (int nt = 0; nt < 8; ++nt)
                    MMA16816(acc[mt][nt], aR[mt], &bR[nt >> 1][(nt & 1) * 2]);
        }

        // ---- epilogue: subtract 0.5*cnorm, per-8-code block max, store ----
        const float* cnp = (const float*)(smem1 + SM1_CN + st * 512);
#pragma unroll
        for (int mt = 0; mt < 2; ++mt) {
#pragma unroll
            for (int nt = 0; nt < 8; ++nt) {
                int n0 = wn * 64 + nt * 8 + (lane & 3) * 2;
                float2 cn2 = *(const float2*)(cnp + n0);
                float s0 = fmaf(cn2.x, -0.5f, acc[mt][nt][0]);
                float s1 = fmaf(cn2.y, -0.5f, acc[mt][nt][1]);
                float s2 = fmaf(cn2.x, -0.5f, acc[mt][nt][2]);
                float s3 = fmaf(cn2.y, -0.5f, acc[mt][nt][3]);
                float v0 = fmaxf(s0, s1);    // row (lane>>2)
                float v1 = fmaxf(s2, s3);    // row (lane>>2)+8
                v0 = fmaxf(v0, __shfl_xor_sync(0xffffffffu, v0, 1));
                v0 = fmaxf(v0, __shfl_xor_sync(0xffffffffu, v0, 2));
                v1 = fmaxf(v1, __shfl_xor_sync(0xffffffffu, v1, 1));
                v1 = fmaxf(v1, __shfl_xor_sync(0xffffffffu, v1, 2));
                if ((lane & 3) == 0) {
                    int m0 = m_base + wm * 32 + mt * 16 + (lane >> 2);
                    int blk = t * 16 + wn * 8 + nt;
                    g_bmax[(size_t)m0 * NBLK + blk] = v0;
                    g_bmax[(size_t)(m0 + 8) * NBLK + blk] = v1;
                }
            }
        }
        CP_WAIT0();
        __syncthreads();
    }
}

// ---------------------------------------------------------------------------
// refine: exact fp32 rescoring of all codes in blocks within the rigorous
// error band of the coarse best. One warp per sample.
// band: |coarse_dot - exact_dot| <= (2*2^-8 + 2^-16)*sum|x_k c_k|
//       <= 0.00785 * ||x|| * max||c||  (+ tiny fp32-accum slack)
// ---------------------------------------------------------------------------
__global__ __launch_bounds__(256)
void refine_kernel(const float* __restrict__ x, const float* __restrict__ cm) {
    int warp = (blockIdx.x * blockDim.x + threadIdx.x) >> 5;
    int lane = threadIdx.x & 31;
    int s = warp;
    const float* bm = &g_bmax[(size_t)s * NBLK];

    // coarse best over blocks
    float best = -INFINITY;
    for (int it = 0; it < 40; ++it) {
        int b = lane + it * 32;
        float v = (b < NBLK) ? bm[b] : -INFINITY;
        best = fmaxf(best, v);
    }
#pragma unroll
    for (int off = 16; off > 0; off >>= 1)
        best = fmaxf(best, __shfl_xor_sync(0xffffffffu, best, off));

    // ||x||^2
    float4 xv = *(const float4*)(x + (size_t)s * EMBED_D + lane * 4);
    float x2 = xv.x * xv.x + xv.y * xv.y + xv.z * xv.z + xv.w * xv.w;
#pragma unroll
    for (int off = 16; off > 0; off >>= 1)
        x2 += __shfl_xor_sync(0xffffffffu, x2, off);

    float cnmax = sqrtf(__int_as_float(g_maxcn_bits));
    float E = 0.0079f * sqrtf(x2) * cnmax + 1e-3f;
    float thr = best - 2.0f * E;

    float bestE = -INFINITY;
    int bestI = 0x7fffffff;
    for (int it = 0; it < 40; ++it) {
        int b = lane + it * 32;
        float v = (b < NBLK) ? bm[b] : -INFINITY;
        unsigned mask = __ballot_sync(0xffffffffu, v >= thr);
        while (mask) {
            int src = __ffs(mask) - 1;
            mask &= mask - 1;
            int bq = src + it * 32;                 // uniform across warp
            int c = bq * 8 + (lane & 7);            // bq <= 1249 -> c < NCODES
            float d = 0.f;
            int k0 = (lane >> 3) * 32;
#pragma unroll 8
            for (int k = k0; k < k0 + 32; ++k)
                d = fmaf(x[(size_t)s * EMBED_D + k], cm[(size_t)k * NCODES + c], d);
            d += __shfl_xor_sync(0xffffffffu, d, 8);
            d += __shfl_xor_sync(0xffffffffu, d, 16);
            float sc = d - 0.5f * g_cnorm[c];
#pragma unroll
            for (int off = 1; off < 8; off <<= 1) {
                float os = __shfl_xor_sync(0xffffffffu, sc, off);
                int   oc = __shfl_xor_sync(0xffffffffu, c, off);
                if (os > sc || (os == sc && oc < c)) { sc = os; c = oc; }
            }
            if (sc > bestE || (sc == bestE && c < bestI)) { bestE = sc; bestI = c; }
        }
    }
    if (lane == 0) g_pidx[s] = bestI;
}

// ---------------------------------------------------------------------------
// combine: gather code, straight-through output, per-block loss partial
// ---------------------------------------------------------------------------
__global__ __launch_bounds__(256)
void combine_kernel(const float* __restrict__ x, const float* __restrict__ cm,
                    float* __restrict__ out) {
    __shared__ float warp_loss[8];
    int warp = threadIdx.x >> 5;
    int lane = threadIdx.x & 31;
    int s = blockIdx.x * 8 + warp;
    int bi = g_pidx[s];

    float lsum = 0.f;
#pragma unroll
    for (int r = 0; r < 4; ++r) {
        int d = r * 32 + lane;
        float xvv = x[(size_t)s * EMBED_D + d];
        float q   = cm[(size_t)d * NCODES + bi];
        float dlt = q - xvv;
        out[(size_t)s * EMBED_D + d] = xvv + dlt;
        lsum = fmaf(dlt, dlt, lsum);
    }
#pragma unroll
    for (int off = 16; off > 0; off >>= 1)
        lsum += __shfl_down_sync(0xffffffffu, lsum, off);
    if (lane == 0) warp_loss[warp] = lsum;
    __syncthreads();
    if (threadIdx.x == 0) {
        double t = 0.0;
        for (int w = 0; w < 8; ++w) t += (double)warp_loss[w];
        g_ploss[blockIdx.x] = t;
    }
}

// ---------------------------------------------------------------------------
// loss: fixed-order parallel reduction; loss = 1.25 * mean((q-x)^2)
// ---------------------------------------------------------------------------
__global__ __launch_bounds__(256)
void loss_kernel(float* __restrict__ out, int out_size) {
    if (out_size <= NSAMP * EMBED_D) return;
    __shared__ double sd[256];
    int tid = threadIdx.x;
    double t = 0.0;
    for (int i = tid; i < NSAMP / 8; i += 256) t += g_ploss[i];
    sd[tid] = t;
    __syncthreads();
#pragma unroll
    for (int off = 128; off > 0; off >>= 1) {
        if (tid < off) sd[tid] += sd[tid + off];
        __syncthreads();
    }
    if (tid == 0)
        out[NSAMP * EMBED_D] = (float)(1.25 * (sd[0] / (double)(NSAMP * EMBED_D)));
}

// ---------------------------------------------------------------------------
extern "C" void kernel_launch(void* const* d_in, const int* in_sizes, int n_in,
                              void* d_out, int out_size) {
    const float* x  = (const float*)d_in[0];   // inputs (8,64,32,128)
    const float* cm = (const float*)d_in[1];   // cluster_mean (128,10000)
    float* out = (float*)d_out;

    (void)cudaFuncSetAttribute(coarse_kernel,
                               cudaFuncAttributeMaxDynamicSharedMemorySize, SM1_TOTAL);

    conv_x_kernel<<<(NSAMP * EMBED_D + 255) / 256, 256>>>(x);
    {
        dim3 g(NPADC / 32, EMBED_D / 32);
        conv_cm_kernel<<<g, 256>>>(cm);
    }
    cnorm_kernel<<<(NPADC + 255) / 256, 256>>>(cm);

    coarse_kernel<<<NSAMP / 128, P1_THREADS, SM1_TOTAL>>>();

    refine_kernel<<<NSAMP / 8, 256>>>(x, cm);
    combine_kernel<<<NSAMP / 8, 256>>>(x, cm, out);
    loss_kernel<<<1, 256>>>(out, out_size);
}

// round 8
// speedup vs baseline: 3.9608x; 1.0266x over previous
#include <cuda_runtime.h>
#include <cuda_bf16.h>
#include <cstdint>
#include <math.h>

// ---------------- problem constants ----------------
#define EMBED_D 128
#define NCODES  10000
#define NPADC   10112          // 79 * 128
#define NSAMP   16384          // 8*64*32
#define NCHUNK  79
#define NBLK    1264           // NPADC / 8 blocks of 8 codes
#define P1_THREADS 512

// smem layout for pass1 (bytes)
#define SM1_A   0              // 128 x 256B (bf16 [m][k], swizzled)
#define SM1_B   32768          // 2 stages x 128 x 256B (bf16 [code][k])
#define SM1_CN  98304          // 2 stages x 128 floats
#define SM1_TOTAL 99328

// ---------------- device scratch ----------------
__device__ __align__(16) __nv_bfloat16 g_xb[NSAMP * EMBED_D];   // [m][k]
__device__ __align__(16) __nv_bfloat16 g_cb[NPADC * EMBED_D];   // [c][k]
__device__ __align__(16) float g_cnorm[NPADC];                  // pad = +inf
__device__ float  g_bmax[(size_t)NSAMP * NBLK];                 // coarse per-8 maxima
__device__ int    g_maxcn_bits = 0;                             // max ||c||^2 (bits)
__device__ int    g_pidx[NSAMP];
__device__ double g_ploss[NSAMP / 8];

// ---------------- PTX helpers (baseline sm_80-class ISA only) ----------------
__device__ __forceinline__ uint32_t smem_u32(const void* p) {
    uint32_t a;
    asm("{ .reg .u64 t; cvta.to.shared.u64 t, %1; cvt.u32.u64 %0, t; }"
        : "=r"(a) : "l"(p));
    return a;
}
#define CP16(dst, src) \
    asm volatile("cp.async.cg.shared.global [%0], [%1], 16;" :: "r"(dst), "l"(src) : "memory")
#define CP_COMMIT() asm volatile("cp.async.commit_group;" ::: "memory")
#define CP_WAIT0()  asm volatile("cp.async.wait_group 0;" ::: "memory")
#define LDM4(r, addr) \
    asm volatile("ldmatrix.sync.aligned.m8n8.x4.shared.b16 {%0,%1,%2,%3}, [%4];" \
        : "=r"((r)[0]), "=r"((r)[1]), "=r"((r)[2]), "=r"((r)[3]) : "r"(addr))
#define MMA16816(d, a, b) \
    asm volatile("mma.sync.aligned.m16n8k16.row.col.f32.bf16.bf16.f32 " \
        "{%0,%1,%2,%3}, {%4,%5,%6,%7}, {%8,%9}, {%0,%1,%2,%3};" \
        : "+f"((d)[0]), "+f"((d)[1]), "+f"((d)[2]), "+f"((d)[3]) \
        : "r"((a)[0]), "r"((a)[1]), "r"((a)[2]), "r"((a)[3]), "r"((b)[0]), "r"((b)[1]))

// ---------------------------------------------------------------------------
// prep: x -> bf16 [m][k]
// ---------------------------------------------------------------------------
__global__ void conv_x_kernel(const float* __restrict__ x) {
    int i = blockIdx.x * blockDim.x + threadIdx.x;
    if (i < NSAMP * EMBED_D) g_xb[i] = __float2bfloat16_rn(x[i]);
}

// ---------------------------------------------------------------------------
// prep: cm [k][c] -> bf16 [c][k], zero-padded codes
// ---------------------------------------------------------------------------
__global__ void conv_cm_kernel(const float* __restrict__ cm) {
    __shared__ float tile[32][33];
    int ct = blockIdx.x, kt = blockIdx.y;
    int tx = threadIdx.x & 31, ty = threadIdx.x >> 5;   // ty 0..7
#pragma unroll
    for (int i = 0; i < 4; ++i) {
        int kr = ty + i * 8;
        int c = ct * 32 + tx;
        tile[kr][tx] = (c < NCODES) ? cm[(size_t)(kt * 32 + kr) * NCODES + c] : 0.f;
    }
    __syncthreads();
#pragma unroll
    for (int i = 0; i < 4; ++i) {
        int cr = ty + i * 8;
        int c = ct * 32 + cr;
        int k = kt * 32 + tx;
        g_cb[(size_t)c * EMBED_D + k] = __float2bfloat16_rn(tile[tx][cr]);
    }
}

// ---------------------------------------------------------------------------
// prep: per-code squared norms (exact fp32), pad=+inf; track max norm
// ---------------------------------------------------------------------------
__global__ void cnorm_kernel(const float* __restrict__ cm) {
    int c = blockIdx.x * blockDim.x + threadIdx.x;
    if (c >= NPADC) return;
    if (c >= NCODES) { g_cnorm[c] = INFINITY; return; }
    float s = 0.f;
#pragma unroll 8
    for (int k = 0; k < EMBED_D; ++k) {
        float v = cm[(size_t)k * NCODES + c];
        s = fmaf(v, v, s);
    }
    g_cnorm[c] = s;
    atomicMax(&g_maxcn_bits, __float_as_int(s));   // positive: int order == float order
}

// ---------------------------------------------------------------------------
// pass 1: coarse bf16 GEMM (mma.sync) + per-8-code block maxima of
// score(s,c) = <x_s, c> - 0.5*||c||^2.
// 128 CTAs x 512 thr (16 warps, 4x4 m/n grid, 32x32 warp tiles);
// CTA owns 128 samples, streams 79 chunks of 128 codes.
// ---------------------------------------------------------------------------
extern __shared__ char smem1[];

__device__ __forceinline__ void p1_load_B(uint32_t sb, int chunk, int st, int tid) {
    int c0 = chunk * 128;
#pragma unroll
    for (int i = 0; i < 4; ++i) {
        int p = tid + i * P1_THREADS;
        int row = p >> 4, c16 = p & 15;
        const __nv_bfloat16* src = &g_cb[(size_t)(c0 + row) * EMBED_D + c16 * 8];
        uint32_t dst = sb + SM1_B + st * 32768 + row * 256 + ((c16 * 16) ^ ((row & 7) << 4));
        CP16(dst, src);
    }
    if (tid < 32)
        CP16(sb + SM1_CN + st * 512 + tid * 16, &g_cnorm[c0 + tid * 4]);
}

__global__ __launch_bounds__(P1_THREADS, 1)
void coarse_kernel() {
    const int tid  = threadIdx.x;
    const int lane = tid & 31;
    const int wid  = tid >> 5;
    const int wm   = wid & 3;          // warp m group: rows wm*32..+31
    const int wn   = wid >> 2;         // warp n group: codes wn*32..+31
    const int m_base = blockIdx.x * 128;
    uint32_t sb = smem_u32(smem1);

    // ---- A tile load: g_xb rows m_base..+127 ----
#pragma unroll
    for (int i = 0; i < 4; ++i) {
        int p = tid + i * P1_THREADS;
        int row = p >> 4, c16 = p & 15;
        const __nv_bfloat16* src = &g_xb[(size_t)(m_base + row) * EMBED_D + c16 * 8];
        uint32_t dst = sb + SM1_A + row * 256 + ((c16 * 16) ^ ((row & 7) << 4));
        CP16(dst, src);
    }
    p1_load_B(sb, 0, 0, tid);
    CP_COMMIT();
    CP_WAIT0();
    __syncthreads();

    // ---- per-lane ldmatrix geometry ----
    // A x4: matrices (m0-7,k0),(m8-15,k0),(m0-7,k8),(m8-15,k8)
    int a_row_loc = (lane & 7) | (lane & 8);
    int a_kb      = (lane & 16);                 // +16B if k+8 half
    uint32_t a_base[2], a_xor[2];
#pragma unroll
    for (int mt = 0; mt < 2; ++mt) {
        int row = wm * 32 + mt * 16 + a_row_loc;
        a_base[mt] = sb + SM1_A + row * 256;
        a_xor[mt]  = (row & 7) << 4;
    }
    // B x4: matrices (nt0,k0),(nt0,k8),(nt1,k0),(nt1,k8) per n16 pair
    int b_row_loc = (lane & 7) | ((lane >> 1) & 8);   // +8 rows for lanes>=16
    int b_kb      = (lane & 8) << 1;                  // +16B for lanes 8-15,24-31
    int b_rowrel[2], b_xor[2];
#pragma unroll
    for (int np = 0; np < 2; ++np) {
        int row = wn * 32 + np * 16 + b_row_loc;
        b_rowrel[np] = row * 256;
        b_xor[np]    = (row & 7) << 4;
    }

    for (int t = 0; t < NCHUNK; ++t) {
        int st = t & 1;
        if (t + 1 < NCHUNK) p1_load_B(sb, t + 1, st ^ 1, tid);
        CP_COMMIT();

        uint32_t bst = sb + SM1_B + st * 32768;
        float acc[2][4][4];
#pragma unroll
        for (int mt = 0; mt < 2; ++mt)
#pragma unroll
            for (int nt = 0; nt < 4; ++nt)
#pragma unroll
                for (int r = 0; r < 4; ++r) acc[mt][nt][r] = 0.f;

#pragma unroll
        for (int ks = 0; ks < 8; ++ks) {
            int kb = ks * 32;
            uint32_t aR[2][4];
#pragma unroll
            for (int mt = 0; mt < 2; ++mt)
                LDM4(aR[mt], a_base[mt] + ((kb + a_kb) ^ a_xor[mt]));
            uint32_t bR[2][4];
#pragma unroll
            for (int np = 0; np < 2; ++np)
                LDM4(bR[np], bst + b_rowrel[np] + ((kb + b_kb) ^ b_xor[np]));
#pragma unroll
            for (int mt = 0; mt < 2; ++mt)
#pragma unroll
                for (int nt = 0; nt < 4; ++nt)
                    MMA16816(acc[mt][nt], aR[mt], &bR[nt >> 1][(nt & 1) * 2]);
        }

        // ---- epilogue: subtract 0.5*cnorm, per-8-code block max, store ----
        const float* cnp = (const float*)(smem1 + SM1_CN + st * 512);
#pragma unroll
        for (int mt = 0; mt < 2; ++mt) {
#pragma unroll
            for (int nt = 0; nt < 4; ++nt) {
                int n0 = wn * 32 + nt * 8 + (lane & 3) * 2;
                float2 cn2 = *(const float2*)(cnp + n0);
                float s0 = fmaf(cn2.x, -0.5f, acc[mt][nt][0]);
                float s1 = fmaf(cn2.y, -0.5f, acc[mt][nt][1]);
                float s2 = fmaf(cn2.x, -0.5f, acc[mt][nt][2]);
                float s3 = fmaf(cn2.y, -0.5f, acc[mt][nt][3]);
                float v0 = fmaxf(s0, s1);    // row (lane>>2)
                float v1 = fmaxf(s2, s3);    // row (lane>>2)+8
                v0 = fmaxf(v0, __shfl_xor_sync(0xffffffffu, v0, 1));
                v0 = fmaxf(v0, __shfl_xor_sync(0xffffffffu, v0, 2));
                v1 = fmaxf(v1, __shfl_xor_sync(0xffffffffu, v1, 1));
                v1 = fmaxf(v1, __shfl_xor_sync(0xffffffffu, v1, 2));
                if ((lane & 3) == 0) {
                    int m0 = m_base + wm * 32 + mt * 16 + (lane >> 2);
                    int blk = t * 16 + wn * 4 + nt;
                    g_bmax[(size_t)m0 * NBLK + blk] = v0;
                    g_bmax[(size_t)(m0 + 8) * NBLK + blk] = v1;
                }
            }
        }
        CP_WAIT0();
        __syncthreads();
    }
}

// ---------------------------------------------------------------------------
// refine: exact fp32 rescoring of all codes in blocks within the rigorous
// error band of the coarse best. One warp per sample.
// band: |coarse_dot - exact_dot| <= (2*2^-8 + 2^-16)*sum|x_k c_k|
//       <= 0.00785 * ||x|| * max||c||  (+ tiny fp32-accum slack)
// ---------------------------------------------------------------------------
__global__ __launch_bounds__(256)
void refine_kernel(const float* __restrict__ x, const float* __restrict__ cm) {
    int warp = (blockIdx.x * blockDim.x + threadIdx.x) >> 5;
    int lane = threadIdx.x & 31;
    int s = warp;
    const float* bm = &g_bmax[(size_t)s * NBLK];

    // coarse best over blocks
    float best = -INFINITY;
    for (int it = 0; it < 40; ++it) {
        int b = lane + it * 32;
        float v = (b < NBLK) ? bm[b] : -INFINITY;
        best = fmaxf(best, v);
    }
#pragma unroll
    for (int off = 16; off > 0; off >>= 1)
        best = fmaxf(best, __shfl_xor_sync(0xffffffffu, best, off));

    // ||x||^2
    float4 xv = *(const float4*)(x + (size_t)s * EMBED_D + lane * 4);
    float x2 = xv.x * xv.x + xv.y * xv.y + xv.z * xv.z + xv.w * xv.w;
#pragma unroll
    for (int off = 16; off > 0; off >>= 1)
        x2 += __shfl_xor_sync(0xffffffffu, x2, off);

    float cnmax = sqrtf(__int_as_float(g_maxcn_bits));
    float E = 0.0079f * sqrtf(x2) * cnmax + 1e-3f;
    float thr = best - 2.0f * E;

    float bestE = -INFINITY;
    int bestI = 0x7fffffff;
    for (int it = 0; it < 40; ++it) {
        int b = lane + it * 32;
        float v = (b < NBLK) ? bm[b] : -INFINITY;
        unsigned mask = __ballot_sync(0xffffffffu, v >= thr);
        while (mask) {
            int src = __ffs(mask) - 1;
            mask &= mask - 1;
            int bq = src + it * 32;                 // uniform across warp
            int c = bq * 8 + (lane & 7);            // bq <= 1249 -> c < NCODES
            float d = 0.f;
            int k0 = (lane >> 3) * 32;
#pragma unroll 8
            for (int k = k0; k < k0 + 32; ++k)
                d = fmaf(x[(size_t)s * EMBED_D + k], cm[(size_t)k * NCODES + c], d);
            d += __shfl_xor_sync(0xffffffffu, d, 8);
            d += __shfl_xor_sync(0xffffffffu, d, 16);
            float sc = d - 0.5f * g_cnorm[c];
#pragma unroll
            for (int off = 1; off < 8; off <<= 1) {
                float os = __shfl_xor_sync(0xffffffffu, sc, off);
                int   oc = __shfl_xor_sync(0xffffffffu, c, off);
                if (os > sc || (os == sc && oc < c)) { sc = os; c = oc; }
            }
            if (sc > bestE || (sc == bestE && c < bestI)) { bestE = sc; bestI = c; }
        }
    }
    if (lane == 0) g_pidx[s] = bestI;
}

// ---------------------------------------------------------------------------
// combine: gather code, straight-through output, per-block loss partial
// ---------------------------------------------------------------------------
__global__ __launch_bounds__(256)
void combine_kernel(const float* __restrict__ x, const float* __restrict__ cm,
                    float* __restrict__ out) {
    __shared__ float warp_loss[8];
    int warp = threadIdx.x >> 5;
    int lane = threadIdx.x & 31;
    int s = blockIdx.x * 8 + warp;
    int bi = g_pidx[s];

    float lsum = 0.f;
#pragma unroll
    for (int r = 0; r < 4; ++r) {
        int d = r * 32 + lane;
        float xvv = x[(size_t)s * EMBED_D + d];
        float q   = cm[(size_t)d * NCODES + bi];
        float dlt = q - xvv;
        out[(size_t)s * EMBED_D + d] = xvv + dlt;
        lsum = fmaf(dlt, dlt, lsum);
    }
#pragma unroll
    for (int off = 16; off > 0; off >>= 1)
        lsum += __shfl_down_sync(0xffffffffu, lsum, off);
    if (lane == 0) warp_loss[warp] = lsum;
    __syncthreads();
    if (threadIdx.x == 0) {
        double t = 0.0;
        for (int w = 0; w < 8; ++w) t += (double)warp_loss[w];
        g_ploss[blockIdx.x] = t;
    }
}

// ---------------------------------------------------------------------------
// loss: fixed-order parallel reduction; loss = 1.25 * mean((q-x)^2)
// ---------------------------------------------------------------------------
__global__ __launch_bounds__(256)
void loss_kernel(float* __restrict__ out, int out_size) {
    if (out_size <= NSAMP * EMBED_D) return;
    __shared__ double sd[256];
    int tid = threadIdx.x;
    double t = 0.0;
    for (int i = tid; i < NSAMP / 8; i += 256) t += g_ploss[i];
    sd[tid] = t;
    __syncthreads();
#pragma unroll
    for (int off = 128; off > 0; off >>= 1) {
        if (tid < off) sd[tid] += sd[tid + off];
        __syncthreads();
    }
    if (tid == 0)
        out[NSAMP * EMBED_D] = (float)(1.25 * (sd[0] / (double)(NSAMP * EMBED_D)));
}

// ---------------------------------------------------------------------------
extern "C" void kernel_launch(void* const* d_in, const int* in_sizes, int n_in,
                              void* d_out, int out_size) {
    const float* x  = (const float*)d_in[0];   // inputs (8,64,32,128)
    const float* cm = (const float*)d_in[1];   // cluster_mean (128,10000)
    float* out = (float*)d_out;

    (void)cudaFuncSetAttribute(coarse_kernel,
                               cudaFuncAttributeMaxDynamicSharedMemorySize, SM1_TOTAL);

    conv_x_kernel<<<(NSAMP * EMBED_D + 255) / 256, 256>>>(x);
    {
        dim3 g(NPADC / 32, EMBED_D / 32);
        conv_cm_kernel<<<g, 256>>>(cm);
    }
    cnorm_kernel<<<(NPADC + 255) / 256, 256>>>(cm);

    coarse_kernel<<<NSAMP / 128, P1_THREADS, SM1_TOTAL>>>();

    refine_kernel<<<NSAMP / 8, 256>>>(x, cm);
    combine_kernel<<<NSAMP / 8, 256>>>(x, cm, out);
    loss_kernel<<<1, 256>>>(out, out_size);
}